// round 7
// baseline (speedup 1.0000x reference)
#include <cuda_runtime.h>
#include <cuda_bf16.h>
#include <cstdint>

// ---------------------------------------------------------------------------
// Problem constants
// ---------------------------------------------------------------------------
#define M_DIM 256
#define K_DIM 4096
#define N_DIM 11008
#define G_DIM 32
#define R_DIM 16
#define SCALING 2.0f

#define BM 64
#define BN 128
#define BK 64
#define KT (K_DIM / BK)     // 64

// SMEM: A tiles [64 rows][64 s8] pitch 80 (hi + lo), B tiles [128 rows][64 s8] pitch 80.
#define PITCH  80
#define A_MAT  5120                  // 64*80
#define A_ST   10240                 // hi + lo
#define A_LOOFF 5120
#define NSTG   4
#define B_BASE (NSTG * A_ST)         // 40960
#define B_ST   10240                 // 128*80
#define SXA    (B_BASE + NSTG * B_ST)   // 81920  lora xa [64][16] bf16 pitch 32
#define SLB    (SXA + 2048)             // 83968  lora B [128][16] bf16 pitch 32
#define SMEM_BYTES (SLB + 4096)         // 88064

// Global scratch
__device__ __align__(16) float g_xa[M_DIM * R_DIM];
__device__ __align__(16) float g_sx[M_DIM * G_DIM];              // per (m, group) scale
__device__ __align__(16) char  g_xh8[(size_t)M_DIM * K_DIM];     // x hi s8
__device__ __align__(16) char  g_xl8[(size_t)M_DIM * K_DIM];     // x lo s8
__device__ __align__(16) char  g_qw8[(size_t)N_DIM * K_DIM];     // w8 = q - z

// ---------------------------------------------------------------------------
// helpers (family-common PTX)
// ---------------------------------------------------------------------------
__device__ __forceinline__ uint32_t smem_u32(const void* p) {
    uint32_t a;
    asm("{ .reg .u64 t; cvta.to.shared.u64 t, %1; cvt.u32.u64 %0, t; }"
        : "=r"(a) : "l"(p));
    return a;
}
__device__ __forceinline__ void ldsm_x4(uint32_t addr, uint32_t* r) {
    asm volatile("ldmatrix.sync.aligned.m8n8.x4.shared.b16 {%0,%1,%2,%3}, [%4];"
                 : "=r"(r[0]), "=r"(r[1]), "=r"(r[2]), "=r"(r[3]) : "r"(addr));
}
__device__ __forceinline__ void ldsm_x2(uint32_t addr, uint32_t* r) {
    asm volatile("ldmatrix.sync.aligned.m8n8.x2.shared.b16 {%0,%1}, [%2];"
                 : "=r"(r[0]), "=r"(r[1]) : "r"(addr));
}
__device__ __forceinline__ void mma_s8(int* c, const uint32_t* a, const uint32_t* b) {
    asm volatile(
        "mma.sync.aligned.m16n8k32.row.col.s32.s8.s8.s32 "
        "{%0,%1,%2,%3}, {%4,%5,%6,%7}, {%8,%9}, {%0,%1,%2,%3};"
        : "+r"(c[0]), "+r"(c[1]), "+r"(c[2]), "+r"(c[3])
        : "r"(a[0]), "r"(a[1]), "r"(a[2]), "r"(a[3]), "r"(b[0]), "r"(b[1]));
}
__device__ __forceinline__ void mma_bf16(float* c, const uint32_t* a, const uint32_t* b) {
    asm volatile(
        "mma.sync.aligned.m16n8k16.row.col.f32.bf16.bf16.f32 "
        "{%0,%1,%2,%3}, {%4,%5,%6,%7}, {%8,%9}, {%0,%1,%2,%3};"
        : "+f"(c[0]), "+f"(c[1]), "+f"(c[2]), "+f"(c[3])
        : "r"(a[0]), "r"(a[1]), "r"(a[2]), "r"(a[3]), "r"(b[0]), "r"(b[1]));
}
__device__ __forceinline__ void cpa16(uint32_t dst, const void* src) {
    asm volatile("cp.async.cg.shared.global [%0], [%1], 16;"
                 :: "r"(dst), "l"(src) : "memory");
}
__device__ __forceinline__ void cpa_commit() {
    asm volatile("cp.async.commit_group;" ::: "memory");
}
__device__ __forceinline__ void cpa_wait2() {
    asm volatile("cp.async.wait_group 2;" ::: "memory");
}
__device__ __forceinline__ uint32_t pack_bf16(float v0, float v1) {
    __nv_bfloat162 p = __floats2bfloat162_rn(v0, v1);
    return *reinterpret_cast<uint32_t*>(&p);
}

// ---------------------------------------------------------------------------
// Kernel 0a: quantize x per (m, 128-group): x = sx * (256*hi + lo), hi/lo s8.
// One warp per group.
// ---------------------------------------------------------------------------
__global__ __launch_bounds__(256)
void xquant_kernel(const float* __restrict__ x) {
    const int wid  = threadIdx.x >> 5;
    const int lane = threadIdx.x & 31;
    const int gid  = blockIdx.x * 8 + wid;          // 0..8191
    const int m = gid >> 5, g = gid & 31;

    const float4* src = reinterpret_cast<const float4*>(x + (size_t)m * K_DIM + g * 128);
    float4 v = src[lane];
    float amax = fmaxf(fmaxf(fabsf(v.x), fabsf(v.y)), fmaxf(fabsf(v.z), fabsf(v.w)));
#pragma unroll
    for (int o = 16; o > 0; o >>= 1)
        amax = fmaxf(amax, __shfl_xor_sync(0xFFFFFFFFu, amax, o));
    amax = fmaxf(amax, 1e-20f);
    const float si = 32512.f / amax;

    int q0 = __float2int_rn(v.x * si);
    int q1 = __float2int_rn(v.y * si);
    int q2 = __float2int_rn(v.z * si);
    int q3 = __float2int_rn(v.w * si);
    int h0 = (q0 + 128) >> 8, h1 = (q1 + 128) >> 8;
    int h2 = (q2 + 128) >> 8, h3 = (q3 + 128) >> 8;
    int l0 = q0 - (h0 << 8), l1 = q1 - (h1 << 8);
    int l2 = q2 - (h2 << 8), l3 = q3 - (h3 << 8);

    uint32_t hp = (uint32_t)(h0 & 0xFF) | ((uint32_t)(h1 & 0xFF) << 8) |
                  ((uint32_t)(h2 & 0xFF) << 16) | ((uint32_t)(h3 & 0xFF) << 24);
    uint32_t lp = (uint32_t)(l0 & 0xFF) | ((uint32_t)(l1 & 0xFF) << 8) |
                  ((uint32_t)(l2 & 0xFF) << 16) | ((uint32_t)(l3 & 0xFF) << 24);

    const size_t o4 = (((size_t)m * K_DIM + g * 128) >> 2) + lane;
    reinterpret_cast<uint32_t*>(g_xh8)[o4] = hp;
    reinterpret_cast<uint32_t*>(g_xl8)[o4] = lp;
    if (lane == 0) g_sx[m * G_DIM + g] = amax * (1.f / 32512.f);
}

// ---------------------------------------------------------------------------
// Kernel 0b: pack w8 = qweight - zeros into s8
// ---------------------------------------------------------------------------
__global__ __launch_bounds__(256)
void pack_qw8(const int* __restrict__ qw, const int* __restrict__ zeros) {
    const size_t base = ((size_t)blockIdx.x * 256 + threadIdx.x) * 8;
    const int o = (int)(base >> 12);
    const int i = (int)(base & 4095);
    const int z = zeros[o * G_DIM + (i >> 7)];
    int4 a = reinterpret_cast<const int4*>(qw + base)[0];
    int4 b = reinterpret_cast<const int4*>(qw + base)[1];
    uint32_t lo = (uint32_t)((a.x - z) & 0xFF)        |
                  ((uint32_t)((a.y - z) & 0xFF) << 8)  |
                  ((uint32_t)((a.z - z) & 0xFF) << 16) |
                  ((uint32_t)((a.w - z) & 0xFF) << 24);
    uint32_t hi = (uint32_t)((b.x - z) & 0xFF)        |
                  ((uint32_t)((b.y - z) & 0xFF) << 8)  |
                  ((uint32_t)((b.z - z) & 0xFF) << 16) |
                  ((uint32_t)((b.w - z) & 0xFF) << 24);
    *reinterpret_cast<uint2*>(g_qw8 + base) = make_uint2(lo, hi);
}

// ---------------------------------------------------------------------------
// Kernel 1: xa[m, r] = SCALING * sum_k x[m,k] * lora_A[r,k]
// ---------------------------------------------------------------------------
__global__ __launch_bounds__(256)
void lora_xa_kernel(const float* __restrict__ x, const float* __restrict__ loraA) {
    const int m   = blockIdx.x;
    const int tid = threadIdx.x;
    const int lid = tid & 31;
    const int wid = tid >> 5;

    float acc[R_DIM];
#pragma unroll
    for (int r = 0; r < R_DIM; r++) acc[r] = 0.f;

    const float4* x4 = reinterpret_cast<const float4*>(x + (size_t)m * K_DIM);
    const float4* a4 = reinterpret_cast<const float4*>(loraA);
#pragma unroll
    for (int i = 0; i < 4; i++) {
        int f = tid + i * 256;
        float4 xv = x4[f];
#pragma unroll
        for (int r = 0; r < R_DIM; r++) {
            float4 av = a4[r * (K_DIM / 4) + f];
            acc[r] = fmaf(xv.x, av.x, acc[r]);
            acc[r] = fmaf(xv.y, av.y, acc[r]);
            acc[r] = fmaf(xv.z, av.z, acc[r]);
            acc[r] = fmaf(xv.w, av.w, acc[r]);
        }
    }
#pragma unroll
    for (int r = 0; r < R_DIM; r++) {
#pragma unroll
        for (int o = 16; o > 0; o >>= 1)
            acc[r] += __shfl_xor_sync(0xFFFFFFFFu, acc[r], o);
    }
    __shared__ float red[8][R_DIM];
    if (lid == 0) {
#pragma unroll
        for (int r = 0; r < R_DIM; r++) red[wid][r] = acc[r];
    }
    __syncthreads();
    if (tid < R_DIM) {
        float v = 0.f;
#pragma unroll
        for (int w = 0; w < 8; w++) v += red[w][tid];
        g_xa[m * R_DIM + tid] = v * SCALING;
    }
}

// ---------------------------------------------------------------------------
// Kernel 2: main GEMM (s8 MMA).
//   P_hi/P_lo accumulate s32 over a 128-k group; tac += sx*s*(256*P_hi + P_lo).
// 256 threads = 8 warps 2(m) x 4(n), warp tile 32x32, 2 CTAs/SM.
// 4-stage cp.async ring for A(hi,lo) and B (raw s8, no dequant in loop).
// ---------------------------------------------------------------------------
__global__ __launch_bounds__(256, 2)
void gptq_lora_mma(const float* __restrict__ scales,
                   const float* __restrict__ loraB,
                   float*       __restrict__ out) {
    extern __shared__ __align__(16) char sm[];
    const uint32_t sb = smem_u32(sm);

    const int tid  = threadIdx.x;
    const int lane = tid & 31;
    const int wid  = tid >> 5;
    const int m0   = blockIdx.x * BM;    // 4 m-tiles
    const int n0   = blockIdx.y * BN;    // 86 n-tiles

    // ---- LoRA tiles (once) ----
    if (tid < 192) {
        const int row = (tid < 64) ? tid : (tid - 64);
        const float* src = (tid < 64)
            ? (g_xa + (size_t)(m0 + row) * R_DIM)
            : (loraB + (size_t)(n0 + row) * R_DIM);
        char* dst = sm + ((tid < 64) ? SXA : SLB) + row * 32;
        float4 v0 = reinterpret_cast<const float4*>(src)[0];
        float4 v1 = reinterpret_cast<const float4*>(src)[1];
        float4 v2 = reinterpret_cast<const float4*>(src)[2];
        float4 v3 = reinterpret_cast<const float4*>(src)[3];
        *reinterpret_cast<uint4*>(dst) =
            make_uint4(pack_bf16(v0.x, v0.y), pack_bf16(v0.z, v0.w),
                       pack_bf16(v1.x, v1.y), pack_bf16(v1.z, v1.w));
        *reinterpret_cast<uint4*>(dst + 16) =
            make_uint4(pack_bf16(v2.x, v2.y), pack_bf16(v2.z, v2.w),
                       pack_bf16(v3.x, v3.y), pack_bf16(v3.z, v3.w));
    }

    // ---- loader mappings (pure cp.async) ----
    // A: 64 rows x 64B per matrix -> 256 chunks; 1 chunk/thread per matrix.
    const int arow = tid >> 2;
    const int achk = (tid & 3) * 16;
    const char* aghi = g_xh8 + (size_t)(m0 + arow) * K_DIM + achk;
    const char* aglo = g_xl8 + (size_t)(m0 + arow) * K_DIM + achk;
    const uint32_t a_soff = (uint32_t)(arow * PITCH + achk);
    // B: 128 rows x 64B -> 512 chunks; 2 chunks/thread (32B contiguous).
    const int brow = tid >> 1;
    const int bko  = (tid & 1) * 32;
    const char* bg = g_qw8 + (size_t)(n0 + brow) * K_DIM + bko;
    const uint32_t b_soff = (uint32_t)(brow * PITCH + bko);

    // ---- prologue: stages 0..2 ----
#pragma unroll
    for (int s = 0; s < 3; s++) {
        cpa16(sb + s * A_ST + a_soff, aghi + s * BK);
        cpa16(sb + s * A_ST + A_LOOFF + a_soff, aglo + s * BK);
        cpa16(sb + B_BASE + s * B_ST + b_soff, bg + s * BK);
        cpa16(sb + B_BASE + s * B_ST + b_soff + 16, bg + s * BK + 16);
        cpa_commit();
    }

    // ---- accumulators / compute mappings ----
    float tac[2][4][4];
    int   pach[2][4][4], pacl[2][4][4];
#pragma unroll
    for (int mi = 0; mi < 2; mi++)
#pragma unroll
        for (int ni = 0; ni < 4; ni++)
#pragma unroll
            for (int j = 0; j < 4; j++) {
                tac[mi][ni][j] = 0.f; pach[mi][ni][j] = 0; pacl[mi][ni][j] = 0;
            }

    const int wm = (wid >> 2) * 32;            // 0/32
    const int wn = (wid & 3) * 32;             // 0..96
    const uint32_t aoff  = (uint32_t)((wm + (lane & 15)) * PITCH + ((lane >> 4) << 4));
    const uint32_t boff4 = (uint32_t)((wn + (lane & 7) + ((lane >> 4) << 3)) * PITCH
                                      + (((lane >> 3) & 1) << 4));
    const float* scp = scales + (size_t)(n0 + wn + (lane & 3) * 2) * G_DIM;
    const float* sxp = g_sx + (size_t)(m0 + wm + (lane >> 2)) * G_DIM;

    cpa_wait2();          // stage 0 ready (<=2 pending of 3 committed)
    __syncthreads();

    for (int kt = 0; kt < KT; kt++) {
        // 1. prefetch stage kt+3
        if (kt < KT - 3) {
            const int ks = kt + 3;
            const int st = ks & 3;
            cpa16(sb + st * A_ST + a_soff, aghi + ks * BK);
            cpa16(sb + st * A_ST + A_LOOFF + a_soff, aglo + ks * BK);
            cpa16(sb + B_BASE + st * B_ST + b_soff, bg + ks * BK);
            cpa16(sb + B_BASE + st * B_ST + b_soff + 16, bg + ks * BK + 16);
        }
        cpa_commit();

        // 2. compute stage kt&3: 2 x k32, hi + lo s8 MMAs
        {
            const uint32_t Ab = sb + (uint32_t)((kt & 3) * A_ST);
            const uint32_t Bb = sb + B_BASE + (uint32_t)((kt & 3) * B_ST);
#pragma unroll
            for (int kk = 0; kk < 2; kk++) {
                const uint32_t kb = (uint32_t)(kk * 32);
                uint32_t ah[2][4], al[2][4], b[4][2];
#pragma unroll
                for (int mi = 0; mi < 2; mi++)
                    ldsm_x4(Ab + aoff + mi * (16 * PITCH) + kb, ah[mi]);
#pragma unroll
                for (int nj = 0; nj < 2; nj++) {
                    uint32_t t[4];
                    ldsm_x4(Bb + boff4 + nj * (16 * PITCH) + kb, t);
                    b[2 * nj][0] = t[0]; b[2 * nj][1] = t[1];
                    b[2 * nj + 1][0] = t[2]; b[2 * nj + 1][1] = t[3];
                }
#pragma unroll
                for (int mi = 0; mi < 2; mi++)
#pragma unroll
                    for (int ni = 0; ni < 4; ni++)
                        mma_s8(pach[mi][ni], ah[mi], b[ni]);
#pragma unroll
                for (int mi = 0; mi < 2; mi++)
                    ldsm_x4(Ab + A_LOOFF + aoff + mi * (16 * PITCH) + kb, al[mi]);
#pragma unroll
                for (int mi = 0; mi < 2; mi++)
#pragma unroll
                    for (int ni = 0; ni < 4; ni++)
                        mma_s8(pacl[mi][ni], al[mi], b[ni]);
            }
        }

        // 3. per-group rescale (group = 128 k = 2 iters)
        if (kt & 1) {
            const int g = kt >> 1;
            float sxv[2][2];
#pragma unroll
            for (int mi = 0; mi < 2; mi++) {
                sxv[mi][0] = sxp[(mi * 16) * G_DIM + g];
                sxv[mi][1] = sxp[(mi * 16 + 8) * G_DIM + g];
            }
#pragma unroll
            for (int ni = 0; ni < 4; ni++) {
                const float s0 = scp[ni * 8 * G_DIM + g];
                const float s1 = scp[ni * 8 * G_DIM + G_DIM + g];
#pragma unroll
                for (int mi = 0; mi < 2; mi++) {
                    const float w00 = sxv[mi][0] * s0, w01 = sxv[mi][0] * s1;
                    const float w10 = sxv[mi][1] * s0, w11 = sxv[mi][1] * s1;
                    int c0 = pach[mi][ni][0] * 256 + pacl[mi][ni][0];
                    int c1 = pach[mi][ni][1] * 256 + pacl[mi][ni][1];
                    int c2 = pach[mi][ni][2] * 256 + pacl[mi][ni][2];
                    int c3 = pach[mi][ni][3] * 256 + pacl[mi][ni][3];
                    tac[mi][ni][0] = fmaf((float)c0, w00, tac[mi][ni][0]);
                    tac[mi][ni][1] = fmaf((float)c1, w01, tac[mi][ni][1]);
                    tac[mi][ni][2] = fmaf((float)c2, w10, tac[mi][ni][2]);
                    tac[mi][ni][3] = fmaf((float)c3, w11, tac[mi][ni][3]);
                    pach[mi][ni][0] = 0; pach[mi][ni][1] = 0;
                    pach[mi][ni][2] = 0; pach[mi][ni][3] = 0;
                    pacl[mi][ni][0] = 0; pacl[mi][ni][1] = 0;
                    pacl[mi][ni][2] = 0; pacl[mi][ni][3] = 0;
                }
            }
        }

        // 4. stage kt+1 ready; publish
        cpa_wait2();
        __syncthreads();
    }

    // ---- LoRA k16 step (bf16 MMA into temp float frags) ----
    {
        uint32_t ah[2][4], b[4][2];
#pragma unroll
        for (int mi = 0; mi < 2; mi++)
            ldsm_x4(sb + SXA + (uint32_t)((wm + mi * 16 + (lane & 15)) * 32
                                          + ((lane >> 4) << 4)), ah[mi]);
#pragma unroll
        for (int ni = 0; ni < 4; ni++)
            ldsm_x2(sb + SLB + (uint32_t)((wn + ni * 8 + (lane & 7)) * 32
                                          + (((lane >> 3) & 1) << 4)), b[ni]);
#pragma unroll
        for (int mi = 0; mi < 2; mi++)
#pragma unroll
            for (int ni = 0; ni < 4; ni++) {
                float t4[4] = {0.f, 0.f, 0.f, 0.f};
                mma_bf16(t4, ah[mi], b[ni]);
#pragma unroll
                for (int j = 0; j < 4; j++)
                    tac[mi][ni][j] += t4[j];
            }
    }

    // ---- store ----
    {
        const int r  = lane >> 2;
        const int c2 = (lane & 3) * 2;
#pragma unroll
        for (int mi = 0; mi < 2; mi++) {
#pragma unroll
            for (int ni = 0; ni < 4; ni++) {
                const int m = m0 + wm + mi * 16 + r;
                const int n = n0 + wn + ni * 8 + c2;
                float* p = out + (size_t)m * N_DIM + n;
                *reinterpret_cast<float2*>(p) =
                    make_float2(tac[mi][ni][0], tac[mi][ni][1]);
                *reinterpret_cast<float2*>(p + 8 * (size_t)N_DIM) =
                    make_float2(tac[mi][ni][2], tac[mi][ni][3]);
            }
        }
    }
}

// ---------------------------------------------------------------------------
// kernel_launch — inputs: x, qweight, scales, zeros, lora_A, lora_B
// ---------------------------------------------------------------------------
extern "C" void kernel_launch(void* const* d_in, const int* in_sizes, int n_in,
                              void* d_out, int out_size) {
    const float* x      = (const float*)d_in[0];
    const int*   qw     = (const int*)  d_in[1];
    const float* scales = (const float*)d_in[2];
    const int*   zeros  = (const int*)  d_in[3];
    const float* loraA  = (const float*)d_in[4];
    const float* loraB  = (const float*)d_in[5];
    float*       out    = (float*)d_out;

    cudaFuncSetAttribute(gptq_lora_mma,
                         cudaFuncAttributeMaxDynamicSharedMemorySize, SMEM_BYTES);

    xquant_kernel<<<(M_DIM * G_DIM) / 8, 256>>>(x);
    pack_qw8<<<(int)(((size_t)N_DIM * K_DIM) / (256 * 8)), 256>>>(qw, zeros);
    lora_xa_kernel<<<M_DIM, 256>>>(x, loraA);

    dim3 grid(M_DIM / BM, N_DIM / BN);   // (4, 86): m fastest -> qw8 L2 dedup
    gptq_lora_mma<<<grid, 256, SMEM_BYTES>>>(scales, loraB, out);
}

// round 8
// speedup vs baseline: 2.3088x; 2.3088x over previous
#include <cuda_runtime.h>
#include <cuda_fp16.h>
#include <cstdint>

// ---------------------------------------------------------------------------
// Problem constants
// ---------------------------------------------------------------------------
#define M_DIM 256
#define K_DIM 4096
#define N_DIM 11008
#define G_DIM 32
#define R_DIM 16
#define SCALING 2.0f

#define BM 64
#define BN 128
#define BK 64
#define KT (K_DIM / BK)     // 64

// SMEM: 4 stages. A [64][64] fp16 pitch 144 (9216 B), B [128][64] fp16 pitch 144 (18432 B).
#define PITCH  144
#define A_ST   9216
#define NSTG   4
#define B_BASE (NSTG * A_ST)          // 36864
#define B_ST   18432
#define SMEM_BYTES (B_BASE + NSTG * B_ST)   // 110592  (2 CTAs/SM fit)
// LoRA tiles reuse stage-0 smem after the main loop:
#define SXA 0        // xa  [64][16] fp16, pitch 32
#define SLB 2048     // lB  [128][16] fp16, pitch 32

// Global scratch
__device__ __align__(16) float  g_xa[M_DIM * R_DIM];
__device__ __align__(16) __half g_x16[(size_t)M_DIM * K_DIM];   // x in fp16
__device__ __align__(16) __half g_w16[(size_t)N_DIM * K_DIM];   // q - z in fp16 (exact)

// ---------------------------------------------------------------------------
// helpers (family-common PTX)
// ---------------------------------------------------------------------------
__device__ __forceinline__ uint32_t smem_u32(const void* p) {
    uint32_t a;
    asm("{ .reg .u64 t; cvta.to.shared.u64 t, %1; cvt.u32.u64 %0, t; }"
        : "=r"(a) : "l"(p));
    return a;
}
__device__ __forceinline__ void ldsm_x4(uint32_t addr, uint32_t* r) {
    asm volatile("ldmatrix.sync.aligned.m8n8.x4.shared.b16 {%0,%1,%2,%3}, [%4];"
                 : "=r"(r[0]), "=r"(r[1]), "=r"(r[2]), "=r"(r[3]) : "r"(addr));
}
__device__ __forceinline__ void ldsm_x2(uint32_t addr, uint32_t* r) {
    asm volatile("ldmatrix.sync.aligned.m8n8.x2.shared.b16 {%0,%1}, [%2];"
                 : "=r"(r[0]), "=r"(r[1]) : "r"(addr));
}
__device__ __forceinline__ void mma_f16(float* c, const uint32_t* a, const uint32_t* b) {
    asm volatile(
        "mma.sync.aligned.m16n8k16.row.col.f32.f16.f16.f32 "
        "{%0,%1,%2,%3}, {%4,%5,%6,%7}, {%8,%9}, {%0,%1,%2,%3};"
        : "+f"(c[0]), "+f"(c[1]), "+f"(c[2]), "+f"(c[3])
        : "r"(a[0]), "r"(a[1]), "r"(a[2]), "r"(a[3]), "r"(b[0]), "r"(b[1]));
}
__device__ __forceinline__ void cpa16(uint32_t dst, const void* src) {
    asm volatile("cp.async.cg.shared.global [%0], [%1], 16;"
                 :: "r"(dst), "l"(src) : "memory");
}
__device__ __forceinline__ void cpa_commit() {
    asm volatile("cp.async.commit_group;" ::: "memory");
}
__device__ __forceinline__ void cpa_wait2() {
    asm volatile("cp.async.wait_group 2;" ::: "memory");
}
__device__ __forceinline__ uint32_t pack_f16(float v0, float v1) {
    __half2 p = __floats2half2_rn(v0, v1);
    return *reinterpret_cast<uint32_t*>(&p);
}

// ---------------------------------------------------------------------------
// Kernel 0a: x -> fp16
// ---------------------------------------------------------------------------
__global__ __launch_bounds__(256)
void x16_kernel(const float* __restrict__ x) {
    const size_t i8 = ((size_t)blockIdx.x * 256 + threadIdx.x) * 8;
    float4 v0 = reinterpret_cast<const float4*>(x + i8)[0];
    float4 v1 = reinterpret_cast<const float4*>(x + i8)[1];
    uint4 o;
    o.x = pack_f16(v0.x, v0.y);
    o.y = pack_f16(v0.z, v0.w);
    o.z = pack_f16(v1.x, v1.y);
    o.w = pack_f16(v1.z, v1.w);
    *reinterpret_cast<uint4*>(g_x16 + i8) = o;
}

// ---------------------------------------------------------------------------
// Kernel 0b: w16 = (qweight - zeros) in fp16 (exact, [-15,15])
// ---------------------------------------------------------------------------
__global__ __launch_bounds__(256)
void pack_w16(const int* __restrict__ qw, const int* __restrict__ zeros) {
    const size_t base = ((size_t)blockIdx.x * 256 + threadIdx.x) * 8;
    const int o = (int)(base >> 12);
    const int i = (int)(base & 4095);
    const int z = zeros[o * G_DIM + (i >> 7)];
    int4 a = reinterpret_cast<const int4*>(qw + base)[0];
    int4 b = reinterpret_cast<const int4*>(qw + base)[1];
    uint4 w;
    w.x = pack_f16((float)(a.x - z), (float)(a.y - z));
    w.y = pack_f16((float)(a.z - z), (float)(a.w - z));
    w.z = pack_f16((float)(b.x - z), (float)(b.y - z));
    w.w = pack_f16((float)(b.z - z), (float)(b.w - z));
    *reinterpret_cast<uint4*>(g_w16 + base) = w;
}

// ---------------------------------------------------------------------------
// Kernel 1: xa[m, r] = SCALING * sum_k x[m,k] * lora_A[r,k]
// ---------------------------------------------------------------------------
__global__ __launch_bounds__(256)
void lora_xa_kernel(const float* __restrict__ x, const float* __restrict__ loraA) {
    const int m   = blockIdx.x;
    const int tid = threadIdx.x;
    const int lid = tid & 31;
    const int wid = tid >> 5;

    float acc[R_DIM];
#pragma unroll
    for (int r = 0; r < R_DIM; r++) acc[r] = 0.f;

    const float4* x4 = reinterpret_cast<const float4*>(x + (size_t)m * K_DIM);
    const float4* a4 = reinterpret_cast<const float4*>(loraA);
#pragma unroll
    for (int i = 0; i < 4; i++) {
        int f = tid + i * 256;
        float4 xv = x4[f];
#pragma unroll
        for (int r = 0; r < R_DIM; r++) {
            float4 av = a4[r * (K_DIM / 4) + f];
            acc[r] = fmaf(xv.x, av.x, acc[r]);
            acc[r] = fmaf(xv.y, av.y, acc[r]);
            acc[r] = fmaf(xv.z, av.z, acc[r]);
            acc[r] = fmaf(xv.w, av.w, acc[r]);
        }
    }
#pragma unroll
    for (int r = 0; r < R_DIM; r++) {
#pragma unroll
        for (int o = 16; o > 0; o >>= 1)
            acc[r] += __shfl_xor_sync(0xFFFFFFFFu, acc[r], o);
    }
    __shared__ float red[8][R_DIM];
    if (lid == 0) {
#pragma unroll
        for (int r = 0; r < R_DIM; r++) red[wid][r] = acc[r];
    }
    __syncthreads();
    if (tid < R_DIM) {
        float v = 0.f;
#pragma unroll
        for (int w = 0; w < 8; w++) v += red[w][tid];
        g_xa[m * R_DIM + tid] = v * SCALING;
    }
}

// ---------------------------------------------------------------------------
// Kernel 2: main GEMM (fp16 HMMA, no in-loop dequant, pure cp.async).
//   pac += x16 * w16 per group (f32 acc);  tac += s[n,g] * pac per group.
//   + LoRA k16 step at the end (lora tiles built in reused stage-0 smem).
// 256 threads = 8 warps 2(m) x 4(n), warp tile 32x32, 2 CTAs/SM, 4-stage ring.
// ---------------------------------------------------------------------------
__global__ __launch_bounds__(256, 2)
void gptq_lora_mma(const float* __restrict__ scales,
                   const float* __restrict__ loraB,
                   float*       __restrict__ out) {
    extern __shared__ __align__(16) char sm[];
    const uint32_t sb = smem_u32(sm);

    const int tid  = threadIdx.x;
    const int lane = tid & 31;
    const int wid  = tid >> 5;
    const int m0   = blockIdx.x * BM;    // 4 m-tiles
    const int n0   = blockIdx.y * BN;    // 86 n-tiles

    // ---- loader mappings ----
    // A: 64 rows x 128B -> 512 chunks; 2 contiguous chunks/thread.
    const int arow = tid >> 2;
    const int acho = (tid & 3) * 32;                     // byte offset in row
    const __half* ag = g_x16 + (size_t)(m0 + arow) * K_DIM + (acho >> 1);
    const uint32_t a_soff = (uint32_t)(arow * PITCH + acho);
    // B: 128 rows x 128B -> 1024 chunks; 4 contiguous chunks/thread.
    const int brow = tid >> 1;
    const int bko  = (tid & 1) * 64;                     // byte offset in row
    const __half* bg = g_w16 + (size_t)(n0 + brow) * K_DIM + (bko >> 1);
    const uint32_t b_soff = (uint32_t)(brow * PITCH + bko);

    // ---- prologue: stages 0..2 ----
#pragma unroll
    for (int s = 0; s < 3; s++) {
        const uint32_t As = sb + s * A_ST;
        const uint32_t Bs = sb + B_BASE + s * B_ST;
        cpa16(As + a_soff,      ag + s * BK);
        cpa16(As + a_soff + 16, ag + s * BK + 8);
        cpa16(Bs + b_soff,      bg + s * BK);
        cpa16(Bs + b_soff + 16, bg + s * BK + 8);
        cpa16(Bs + b_soff + 32, bg + s * BK + 16);
        cpa16(Bs + b_soff + 48, bg + s * BK + 24);
        cpa_commit();
    }

    // ---- accumulators / compute mappings ----
    float tac[2][4][4], pac[2][4][4];
#pragma unroll
    for (int mi = 0; mi < 2; mi++)
#pragma unroll
        for (int ni = 0; ni < 4; ni++)
#pragma unroll
            for (int j = 0; j < 4; j++) { tac[mi][ni][j] = 0.f; pac[mi][ni][j] = 0.f; }

    const int wm = (wid >> 2) * 32;            // 0/32
    const int wn = (wid & 3) * 32;             // 0..96
    const uint32_t aoff  = (uint32_t)((wm + (lane & 15)) * PITCH + ((lane >> 4) << 4));
    const uint32_t boff4 = (uint32_t)((wn + (lane & 7) + ((lane >> 4) << 3)) * PITCH
                                      + (((lane >> 3) & 1) << 4));
    const float* scp = scales + (size_t)(n0 + wn + (lane & 3) * 2) * G_DIM;

    cpa_wait2();          // stage 0 complete
    __syncthreads();

    for (int kt = 0; kt < KT; kt++) {
        // 1. prefetch stage kt+3 (stage computed at kt-1; barrier-protected)
        if (kt < KT - 3) {
            const int ks = kt + 3;
            const int st = ks & 3;
            const uint32_t As = sb + st * A_ST;
            const uint32_t Bs = sb + B_BASE + st * B_ST;
            cpa16(As + a_soff,      ag + ks * BK);
            cpa16(As + a_soff + 16, ag + ks * BK + 8);
            cpa16(Bs + b_soff,      bg + ks * BK);
            cpa16(Bs + b_soff + 16, bg + ks * BK + 8);
            cpa16(Bs + b_soff + 32, bg + ks * BK + 16);
            cpa16(Bs + b_soff + 48, bg + ks * BK + 24);
        }
        cpa_commit();

        // 2. compute stage kt&3: 4 x k16 HMMA
        {
            const uint32_t Ab = sb + (uint32_t)((kt & 3) * A_ST);
            const uint32_t Bb = sb + B_BASE + (uint32_t)((kt & 3) * B_ST);
#pragma unroll
            for (int kk = 0; kk < 4; kk++) {
                const uint32_t kb = (uint32_t)(kk * 32);
                uint32_t ah[2][4], b[4][2];
#pragma unroll
                for (int mi = 0; mi < 2; mi++)
                    ldsm_x4(Ab + aoff + mi * (16 * PITCH) + kb, ah[mi]);
#pragma unroll
                for (int nj = 0; nj < 2; nj++) {
                    uint32_t t[4];
                    ldsm_x4(Bb + boff4 + nj * (16 * PITCH) + kb, t);
                    b[2 * nj][0] = t[0]; b[2 * nj][1] = t[1];
                    b[2 * nj + 1][0] = t[2]; b[2 * nj + 1][1] = t[3];
                }
#pragma unroll
                for (int mi = 0; mi < 2; mi++)
#pragma unroll
                    for (int ni = 0; ni < 4; ni++)
                        mma_f16(pac[mi][ni], ah[mi], b[ni]);
            }
        }

        // 3. per-group rescale (group = 128 k = 2 iters): tac += s * pac
        if (kt & 1) {
            const int g = kt >> 1;
#pragma unroll
            for (int ni = 0; ni < 4; ni++) {
                const float s0 = scp[ni * 8 * G_DIM + g];
                const float s1 = scp[ni * 8 * G_DIM + G_DIM + g];
#pragma unroll
                for (int mi = 0; mi < 2; mi++) {
                    tac[mi][ni][0] = fmaf(pac[mi][ni][0], s0, tac[mi][ni][0]);
                    tac[mi][ni][1] = fmaf(pac[mi][ni][1], s1, tac[mi][ni][1]);
                    tac[mi][ni][2] = fmaf(pac[mi][ni][2], s0, tac[mi][ni][2]);
                    tac[mi][ni][3] = fmaf(pac[mi][ni][3], s1, tac[mi][ni][3]);
                    pac[mi][ni][0] = 0.f; pac[mi][ni][1] = 0.f;
                    pac[mi][ni][2] = 0.f; pac[mi][ni][3] = 0.f;
                }
            }
        }

        // 4. stage kt+1 complete; publish
        cpa_wait2();
        __syncthreads();
    }

    // ---- LoRA tiles: reuse stage-0 smem (all compute done) ----
    if (tid < 192) {
        const int row = (tid < 64) ? tid : (tid - 64);
        const float* src = (tid < 64)
            ? (g_xa + (size_t)(m0 + row) * R_DIM)
            : (loraB + (size_t)(n0 + row) * R_DIM);
        char* dst = sm + ((tid < 64) ? SXA : SLB) + row * 32;
        float4 v0 = reinterpret_cast<const float4*>(src)[0];
        float4 v1 = reinterpret_cast<const float4*>(src)[1];
        float4 v2 = reinterpret_cast<const float4*>(src)[2];
        float4 v3 = reinterpret_cast<const float4*>(src)[3];
        *reinterpret_cast<uint4*>(dst) =
            make_uint4(pack_f16(v0.x, v0.y), pack_f16(v0.z, v0.w),
                       pack_f16(v1.x, v1.y), pack_f16(v1.z, v1.w));
        *reinterpret_cast<uint4*>(dst + 16) =
            make_uint4(pack_f16(v2.x, v2.y), pack_f16(v2.z, v2.w),
                       pack_f16(v3.x, v3.y), pack_f16(v3.z, v3.w));
    }
    __syncthreads();

    // ---- LoRA k16 step (pac is zero after final rescale) ----
    {
        uint32_t ah[2][4], b[4][2];
#pragma unroll
        for (int mi = 0; mi < 2; mi++)
            ldsm_x4(sb + SXA + (uint32_t)((wm + mi * 16 + (lane & 15)) * 32
                                          + ((lane >> 4) << 4)), ah[mi]);
#pragma unroll
        for (int ni = 0; ni < 4; ni++)
            ldsm_x2(sb + SLB + (uint32_t)((wn + ni * 8 + (lane & 7)) * 32
                                          + (((lane >> 3) & 1) << 4)), b[ni]);
#pragma unroll
        for (int mi = 0; mi < 2; mi++)
#pragma unroll
            for (int ni = 0; ni < 4; ni++) {
                mma_f16(pac[mi][ni], ah[mi], b[ni]);
#pragma unroll
                for (int j = 0; j < 4; j++)
                    tac[mi][ni][j] += pac[mi][ni][j];
            }
    }

    // ---- store ----
    {
        const int r  = lane >> 2;
        const int c2 = (lane & 3) * 2;
#pragma unroll
        for (int mi = 0; mi < 2; mi++) {
#pragma unroll
            for (int ni = 0; ni < 4; ni++) {
                const int m = m0 + wm + mi * 16 + r;
                const int n = n0 + wn + ni * 8 + c2;
                float* p = out + (size_t)m * N_DIM + n;
                *reinterpret_cast<float2*>(p) =
                    make_float2(tac[mi][ni][0], tac[mi][ni][1]);
                *reinterpret_cast<float2*>(p + 8 * (size_t)N_DIM) =
                    make_float2(tac[mi][ni][2], tac[mi][ni][3]);
            }
        }
    }
}

// ---------------------------------------------------------------------------
// kernel_launch — inputs: x, qweight, scales, zeros, lora_A, lora_B
// ---------------------------------------------------------------------------
extern "C" void kernel_launch(void* const* d_in, const int* in_sizes, int n_in,
                              void* d_out, int out_size) {
    const float* x      = (const float*)d_in[0];
    const int*   qw     = (const int*)  d_in[1];
    const float* scales = (const float*)d_in[2];
    const int*   zeros  = (const int*)  d_in[3];
    const float* loraA  = (const float*)d_in[4];
    const float* loraB  = (const float*)d_in[5];
    float*       out    = (float*)d_out;

    cudaFuncSetAttribute(gptq_lora_mma,
                         cudaFuncAttributeMaxDynamicSharedMemorySize, SMEM_BYTES);

    x16_kernel<<<(int)(((size_t)M_DIM * K_DIM) / (256 * 8)), 256>>>(x);
    pack_w16<<<(int)(((size_t)N_DIM * K_DIM) / (256 * 8)), 256>>>(qw, zeros);
    lora_xa_kernel<<<M_DIM, 256>>>(x, loraA);

    dim3 grid(M_DIM / BM, N_DIM / BN);   // (4, 86): m fastest -> w16 L2 dedup
    gptq_lora_mma<<<grid, 256, SMEM_BYTES>>>(scales, loraB, out);
}

// round 9
// speedup vs baseline: 2.5286x; 1.0952x over previous
#include <cuda_runtime.h>
#include <cuda_fp16.h>
#include <cstdint>

// ---------------------------------------------------------------------------
// Problem constants
// ---------------------------------------------------------------------------
#define M_DIM 256
#define K_DIM 4096
#define N_DIM 11008
#define G_DIM 32
#define R_DIM 16
#define SCALING 2.0f

#define BM 64
#define BN 128
#define BK 64
#define KT (K_DIM / BK)     // 64

// SMEM: 4 stages. A [64][64] fp16 pitch 144 (9216 B), B [128][64] fp16 pitch 144 (18432 B).
#define PITCH  144
#define A_ST   9216
#define NSTG   4
#define B_BASE (NSTG * A_ST)          // 36864
#define B_ST   18432
#define SMEM_BYTES (B_BASE + NSTG * B_ST)   // 110592  (2 CTAs/SM)
// LoRA tiles reuse stage-0 smem after the main loop:
#define SXA 0        // xa  [64][16] fp16, pitch 32
#define SLB 2048     // lB  [128][16] fp16, pitch 32

// Global scratch
__device__ __align__(16) float  g_xa[M_DIM * R_DIM];
__device__ __align__(16) __half g_x16[(size_t)M_DIM * K_DIM];   // x in fp16
__device__ __align__(16) __half g_w16[(size_t)N_DIM * K_DIM];   // (q-z)*s in fp16

// ---------------------------------------------------------------------------
// helpers (family-common PTX)
// ---------------------------------------------------------------------------
__device__ __forceinline__ uint32_t smem_u32(const void* p) {
    uint32_t a;
    asm("{ .reg .u64 t; cvta.to.shared.u64 t, %1; cvt.u32.u64 %0, t; }"
        : "=r"(a) : "l"(p));
    return a;
}
__device__ __forceinline__ void ldsm_x4(uint32_t addr, uint32_t* r) {
    asm volatile("ldmatrix.sync.aligned.m8n8.x4.shared.b16 {%0,%1,%2,%3}, [%4];"
                 : "=r"(r[0]), "=r"(r[1]), "=r"(r[2]), "=r"(r[3]) : "r"(addr));
}
__device__ __forceinline__ void ldsm_x2(uint32_t addr, uint32_t* r) {
    asm volatile("ldmatrix.sync.aligned.m8n8.x2.shared.b16 {%0,%1}, [%2];"
                 : "=r"(r[0]), "=r"(r[1]) : "r"(addr));
}
__device__ __forceinline__ void mma_f16(float* c, const uint32_t* a, const uint32_t* b) {
    asm volatile(
        "mma.sync.aligned.m16n8k16.row.col.f32.f16.f16.f32 "
        "{%0,%1,%2,%3}, {%4,%5,%6,%7}, {%8,%9}, {%0,%1,%2,%3};"
        : "+f"(c[0]), "+f"(c[1]), "+f"(c[2]), "+f"(c[3])
        : "r"(a[0]), "r"(a[1]), "r"(a[2]), "r"(a[3]), "r"(b[0]), "r"(b[1]));
}
__device__ __forceinline__ void cpa16(uint32_t dst, const void* src) {
    asm volatile("cp.async.cg.shared.global [%0], [%1], 16;"
                 :: "r"(dst), "l"(src) : "memory");
}
__device__ __forceinline__ void cpa_commit() {
    asm volatile("cp.async.commit_group;" ::: "memory");
}
__device__ __forceinline__ void cpa_wait2() {
    asm volatile("cp.async.wait_group 2;" ::: "memory");
}
__device__ __forceinline__ uint32_t pack_f16(float v0, float v1) {
    __half2 p = __floats2half2_rn(v0, v1);
    return *reinterpret_cast<uint32_t*>(&p);
}

// ---------------------------------------------------------------------------
// Kernel 0a: x -> fp16
// ---------------------------------------------------------------------------
__global__ __launch_bounds__(256)
void x16_kernel(const float* __restrict__ x) {
    const size_t i8 = ((size_t)blockIdx.x * 256 + threadIdx.x) * 8;
    float4 v0 = reinterpret_cast<const float4*>(x + i8)[0];
    float4 v1 = reinterpret_cast<const float4*>(x + i8)[1];
    uint4 o;
    o.x = pack_f16(v0.x, v0.y);
    o.y = pack_f16(v0.z, v0.w);
    o.z = pack_f16(v1.x, v1.y);
    o.w = pack_f16(v1.z, v1.w);
    *reinterpret_cast<uint4*>(g_x16 + i8) = o;
}

// ---------------------------------------------------------------------------
// Kernel 0b: w16 = (qweight - zeros) * scales in fp16 (scale folded in)
// ---------------------------------------------------------------------------
__global__ __launch_bounds__(256)
void pack_w16(const int* __restrict__ qw, const int* __restrict__ zeros,
              const float* __restrict__ scales) {
    const size_t base = ((size_t)blockIdx.x * 256 + threadIdx.x) * 8;
    const int o = (int)(base >> 12);
    const int i = (int)(base & 4095);
    const int g = o * G_DIM + (i >> 7);
    const float z = (float)zeros[g];
    const float s = scales[g];
    const float nz = -z * s;
    int4 a = reinterpret_cast<const int4*>(qw + base)[0];
    int4 b = reinterpret_cast<const int4*>(qw + base)[1];
    uint4 w;
    w.x = pack_f16(fmaf((float)a.x, s, nz), fmaf((float)a.y, s, nz));
    w.y = pack_f16(fmaf((float)a.z, s, nz), fmaf((float)a.w, s, nz));
    w.z = pack_f16(fmaf((float)b.x, s, nz), fmaf((float)b.y, s, nz));
    w.w = pack_f16(fmaf((float)b.z, s, nz), fmaf((float)b.w, s, nz));
    *reinterpret_cast<uint4*>(g_w16 + base) = w;
}

// ---------------------------------------------------------------------------
// Kernel 1: xa[m, r] = SCALING * sum_k x[m,k] * lora_A[r,k]
// ---------------------------------------------------------------------------
__global__ __launch_bounds__(256)
void lora_xa_kernel(const float* __restrict__ x, const float* __restrict__ loraA) {
    const int m   = blockIdx.x;
    const int tid = threadIdx.x;
    const int lid = tid & 31;
    const int wid = tid >> 5;

    float acc[R_DIM];
#pragma unroll
    for (int r = 0; r < R_DIM; r++) acc[r] = 0.f;

    const float4* x4 = reinterpret_cast<const float4*>(x + (size_t)m * K_DIM);
    const float4* a4 = reinterpret_cast<const float4*>(loraA);
#pragma unroll
    for (int i = 0; i < 4; i++) {
        int f = tid + i * 256;
        float4 xv = x4[f];
#pragma unroll
        for (int r = 0; r < R_DIM; r++) {
            float4 av = a4[r * (K_DIM / 4) + f];
            acc[r] = fmaf(xv.x, av.x, acc[r]);
            acc[r] = fmaf(xv.y, av.y, acc[r]);
            acc[r] = fmaf(xv.z, av.z, acc[r]);
            acc[r] = fmaf(xv.w, av.w, acc[r]);
        }
    }
#pragma unroll
    for (int r = 0; r < R_DIM; r++) {
#pragma unroll
        for (int o = 16; o > 0; o >>= 1)
            acc[r] += __shfl_xor_sync(0xFFFFFFFFu, acc[r], o);
    }
    __shared__ float red[8][R_DIM];
    if (lid == 0) {
#pragma unroll
        for (int r = 0; r < R_DIM; r++) red[wid][r] = acc[r];
    }
    __syncthreads();
    if (tid < R_DIM) {
        float v = 0.f;
#pragma unroll
        for (int w = 0; w < 8; w++) v += red[w][tid];
        g_xa[m * R_DIM + tid] = v * SCALING;
    }
}

// ---------------------------------------------------------------------------
// Kernel 2: main GEMM (fp16 HMMA, scales pre-folded, pure cp.async,
// register double-buffered fragments). tac accumulates directly in f32.
// 256 threads = 8 warps 2(m) x 4(n), warp tile 32x32, 2 CTAs/SM, 4-stage ring.
// ---------------------------------------------------------------------------
__global__ __launch_bounds__(256, 2)
void gptq_lora_mma(const float* __restrict__ loraB,
                   float*       __restrict__ out) {
    extern __shared__ __align__(16) char sm[];
    const uint32_t sb = smem_u32(sm);

    const int tid  = threadIdx.x;
    const int lane = tid & 31;
    const int wid  = tid >> 5;
    const int m0   = blockIdx.x * BM;    // 4 m-tiles
    const int n0   = blockIdx.y * BN;    // 86 n-tiles

    // ---- loader mappings ----
    const int arow = tid >> 2;
    const int acho = (tid & 3) * 32;
    const __half* ag = g_x16 + (size_t)(m0 + arow) * K_DIM + (acho >> 1);
    const uint32_t a_soff = (uint32_t)(arow * PITCH + acho);
    const int brow = tid >> 1;
    const int bko  = (tid & 1) * 64;
    const __half* bg = g_w16 + (size_t)(n0 + brow) * K_DIM + (bko >> 1);
    const uint32_t b_soff = (uint32_t)(brow * PITCH + bko);

    // ---- prologue: stages 0..2 ----
#pragma unroll
    for (int s = 0; s < 3; s++) {
        const uint32_t As = sb + s * A_ST;
        const uint32_t Bs = sb + B_BASE + s * B_ST;
        cpa16(As + a_soff,      ag + s * BK);
        cpa16(As + a_soff + 16, ag + s * BK + 8);
        cpa16(Bs + b_soff,      bg + s * BK);
        cpa16(Bs + b_soff + 16, bg + s * BK + 8);
        cpa16(Bs + b_soff + 32, bg + s * BK + 16);
        cpa16(Bs + b_soff + 48, bg + s * BK + 24);
        cpa_commit();
    }

    // ---- accumulators / compute mappings ----
    float tac[2][4][4];
#pragma unroll
    for (int mi = 0; mi < 2; mi++)
#pragma unroll
        for (int ni = 0; ni < 4; ni++)
#pragma unroll
            for (int j = 0; j < 4; j++) tac[mi][ni][j] = 0.f;

    const int wm = (wid >> 2) * 32;            // 0/32
    const int wn = (wid & 3) * 32;             // 0..96
    const uint32_t aoff  = (uint32_t)((wm + (lane & 15)) * PITCH + ((lane >> 4) << 4));
    const uint32_t boff4 = (uint32_t)((wn + (lane & 7) + ((lane >> 4) << 3)) * PITCH
                                      + (((lane >> 3) & 1) << 4));

    cpa_wait2();          // stage 0 complete (this thread's groups)
    __syncthreads();      // all threads' groups -> stage 0 fully visible

    // frag double buffers
    uint32_t fa[2][2][4], fb[2][4][2];

    for (int kt = 0; kt < KT; kt++) {
        // 1. prefetch stage kt+3
        if (kt < KT - 3) {
            const int ks = kt + 3;
            const int st = ks & 3;
            const uint32_t As = sb + st * A_ST;
            const uint32_t Bs = sb + B_BASE + st * B_ST;
            cpa16(As + a_soff,      ag + ks * BK);
            cpa16(As + a_soff + 16, ag + ks * BK + 8);
            cpa16(Bs + b_soff,      bg + ks * BK);
            cpa16(Bs + b_soff + 16, bg + ks * BK + 8);
            cpa16(Bs + b_soff + 32, bg + ks * BK + 16);
            cpa16(Bs + b_soff + 48, bg + ks * BK + 24);
        }
        cpa_commit();

        // 2. compute stage kt&3: 4 x k16 HMMA, frag-double-buffered
        {
            const uint32_t Ab = sb + (uint32_t)((kt & 3) * A_ST) + aoff;
            const uint32_t Bb = sb + B_BASE + (uint32_t)((kt & 3) * B_ST) + boff4;

            // load kk=0 into buffer 0
#pragma unroll
            for (int mi = 0; mi < 2; mi++)
                ldsm_x4(Ab + mi * (16 * PITCH), fa[0][mi]);
#pragma unroll
            for (int nj = 0; nj < 2; nj++) {
                uint32_t t[4];
                ldsm_x4(Bb + nj * (16 * PITCH), t);
                fb[0][2 * nj][0] = t[0]; fb[0][2 * nj][1] = t[1];
                fb[0][2 * nj + 1][0] = t[2]; fb[0][2 * nj + 1][1] = t[3];
            }
#pragma unroll
            for (int kk = 0; kk < 4; kk++) {
                const int cur = kk & 1, nxt = cur ^ 1;
                if (kk < 3) {
                    const uint32_t kb = (uint32_t)((kk + 1) * 32);
#pragma unroll
                    for (int mi = 0; mi < 2; mi++)
                        ldsm_x4(Ab + mi * (16 * PITCH) + kb, fa[nxt][mi]);
#pragma unroll
                    for (int nj = 0; nj < 2; nj++) {
                        uint32_t t[4];
                        ldsm_x4(Bb + nj * (16 * PITCH) + kb, t);
                        fb[nxt][2 * nj][0] = t[0]; fb[nxt][2 * nj][1] = t[1];
                        fb[nxt][2 * nj + 1][0] = t[2]; fb[nxt][2 * nj + 1][1] = t[3];
                    }
                }
#pragma unroll
                for (int mi = 0; mi < 2; mi++)
#pragma unroll
                    for (int ni = 0; ni < 4; ni++)
                        mma_f16(tac[mi][ni], fa[cur][mi], fb[cur][ni]);
            }
        }

        // 3. stage kt+1 complete; publish
        cpa_wait2();
        __syncthreads();
    }

    // ---- LoRA tiles: reuse stage-0 smem (all compute done) ----
    if (tid < 192) {
        const int row = (tid < 64) ? tid : (tid - 64);
        const float* src = (tid < 64)
            ? (g_xa + (size_t)(m0 + row) * R_DIM)
            : (loraB + (size_t)(n0 + row) * R_DIM);
        char* dst = sm + ((tid < 64) ? SXA : SLB) + row * 32;
        float4 v0 = reinterpret_cast<const float4*>(src)[0];
        float4 v1 = reinterpret_cast<const float4*>(src)[1];
        float4 v2 = reinterpret_cast<const float4*>(src)[2];
        float4 v3 = reinterpret_cast<const float4*>(src)[3];
        *reinterpret_cast<uint4*>(dst) =
            make_uint4(pack_f16(v0.x, v0.y), pack_f16(v0.z, v0.w),
                       pack_f16(v1.x, v1.y), pack_f16(v1.z, v1.w));
        *reinterpret_cast<uint4*>(dst + 16) =
            make_uint4(pack_f16(v2.x, v2.y), pack_f16(v2.z, v2.w),
                       pack_f16(v3.x, v3.y), pack_f16(v3.z, v3.w));
    }
    __syncthreads();

    // ---- LoRA k16 step ----
    {
        uint32_t ah[2][4], b[4][2];
#pragma unroll
        for (int mi = 0; mi < 2; mi++)
            ldsm_x4(sb + SXA + (uint32_t)((wm + mi * 16 + (lane & 15)) * 32
                                          + ((lane >> 4) << 4)), ah[mi]);
#pragma unroll
        for (int ni = 0; ni < 4; ni++)
            ldsm_x2(sb + SLB + (uint32_t)((wn + ni * 8 + (lane & 7)) * 32
                                          + (((lane >> 3) & 1) << 4)), b[ni]);
#pragma unroll
        for (int mi = 0; mi < 2; mi++)
#pragma unroll
            for (int ni = 0; ni < 4; ni++)
                mma_f16(tac[mi][ni], ah[mi], b[ni]);
    }

    // ---- store ----
    {
        const int r  = lane >> 2;
        const int c2 = (lane & 3) * 2;
#pragma unroll
        for (int mi = 0; mi < 2; mi++) {
#pragma unroll
            for (int ni = 0; ni < 4; ni++) {
                const int m = m0 + wm + mi * 16 + r;
                const int n = n0 + wn + ni * 8 + c2;
                float* p = out + (size_t)m * N_DIM + n;
                *reinterpret_cast<float2*>(p) =
                    make_float2(tac[mi][ni][0], tac[mi][ni][1]);
                *reinterpret_cast<float2*>(p + 8 * (size_t)N_DIM) =
                    make_float2(tac[mi][ni][2], tac[mi][ni][3]);
            }
        }
    }
}

// ---------------------------------------------------------------------------
// kernel_launch — inputs: x, qweight, scales, zeros, lora_A, lora_B
// ---------------------------------------------------------------------------
extern "C" void kernel_launch(void* const* d_in, const int* in_sizes, int n_in,
                              void* d_out, int out_size) {
    const float* x      = (const float*)d_in[0];
    const int*   qw     = (const int*)  d_in[1];
    const float* scales = (const float*)d_in[2];
    const int*   zeros  = (const int*)  d_in[3];
    const float* loraA  = (const float*)d_in[4];
    const float* loraB  = (const float*)d_in[5];
    float*       out    = (float*)d_out;

    cudaFuncSetAttribute(gptq_lora_mma,
                         cudaFuncAttributeMaxDynamicSharedMemorySize, SMEM_BYTES);

    x16_kernel<<<(int)(((size_t)M_DIM * K_DIM) / (256 * 8)), 256>>>(x);
    pack_w16<<<(int)(((size_t)N_DIM * K_DIM) / (256 * 8)), 256>>>(qw, zeros, scales);
    lora_xa_kernel<<<M_DIM, 256>>>(x, loraA);

    dim3 grid(M_DIM / BM, N_DIM / BN);   // (4, 86): m fastest -> w16 L2 dedup
    gptq_lora_mma<<<grid, 256, SMEM_BYTES>>>(loraB, out);
}

// round 10
// speedup vs baseline: 2.8009x; 1.1077x over previous
#include <cuda_runtime.h>
#include <cuda_fp16.h>
#include <cstdint>

// ---------------------------------------------------------------------------
// Problem constants
// ---------------------------------------------------------------------------
#define M_DIM 256
#define K_DIM 4096
#define N_DIM 11008
#define G_DIM 32
#define R_DIM 16
#define SCALING 2.0f

#define BM 64
#define BN 64
#define BK 32
#define KT (K_DIM / BK)     // 128

// SMEM: 4 stages. A [64][32] fp16 pitch 80 (5120 B), B [64][32] fp16 pitch 80.
#define PITCH  80
#define A_ST   5120
#define NSTG   4
#define B_BASE (NSTG * A_ST)              // 20480
#define B_ST   5120
#define SMEM_BYTES (B_BASE + NSTG * B_ST) // 40960  -> 5 CTAs/SM
// LoRA tiles reuse stage-0 smem after the main loop:
#define SXA 0        // xa [64][16] fp16, pitch 32
#define SLB 2048     // lB [64][16] fp16, pitch 32

// Global scratch
__device__ __align__(16) float  g_xa[M_DIM * R_DIM];
__device__ __align__(16) __half g_x16[(size_t)M_DIM * K_DIM];   // x in fp16
__device__ __align__(16) __half g_w16[(size_t)N_DIM * K_DIM];   // (q-z)*s in fp16

// ---------------------------------------------------------------------------
// helpers (family-common PTX)
// ---------------------------------------------------------------------------
__device__ __forceinline__ uint32_t smem_u32(const void* p) {
    uint32_t a;
    asm("{ .reg .u64 t; cvta.to.shared.u64 t, %1; cvt.u32.u64 %0, t; }"
        : "=r"(a) : "l"(p));
    return a;
}
__device__ __forceinline__ void ldsm_x4(uint32_t addr, uint32_t* r) {
    asm volatile("ldmatrix.sync.aligned.m8n8.x4.shared.b16 {%0,%1,%2,%3}, [%4];"
                 : "=r"(r[0]), "=r"(r[1]), "=r"(r[2]), "=r"(r[3]) : "r"(addr));
}
__device__ __forceinline__ void ldsm_x2(uint32_t addr, uint32_t* r) {
    asm volatile("ldmatrix.sync.aligned.m8n8.x2.shared.b16 {%0,%1}, [%2];"
                 : "=r"(r[0]), "=r"(r[1]) : "r"(addr));
}
__device__ __forceinline__ void mma_f16(float* c, const uint32_t* a, const uint32_t* b) {
    asm volatile(
        "mma.sync.aligned.m16n8k16.row.col.f32.f16.f16.f32 "
        "{%0,%1,%2,%3}, {%4,%5,%6,%7}, {%8,%9}, {%0,%1,%2,%3};"
        : "+f"(c[0]), "+f"(c[1]), "+f"(c[2]), "+f"(c[3])
        : "r"(a[0]), "r"(a[1]), "r"(a[2]), "r"(a[3]), "r"(b[0]), "r"(b[1]));
}
__device__ __forceinline__ void cpa16(uint32_t dst, const void* src) {
    asm volatile("cp.async.cg.shared.global [%0], [%1], 16;"
                 :: "r"(dst), "l"(src) : "memory");
}
__device__ __forceinline__ void cpa_commit() {
    asm volatile("cp.async.commit_group;" ::: "memory");
}
__device__ __forceinline__ void cpa_wait2() {
    asm volatile("cp.async.wait_group 2;" ::: "memory");
}
__device__ __forceinline__ uint32_t pack_f16(float v0, float v1) {
    __half2 p = __floats2half2_rn(v0, v1);
    return *reinterpret_cast<uint32_t*>(&p);
}

// ---------------------------------------------------------------------------
// Kernel 0a: x -> fp16
// ---------------------------------------------------------------------------
__global__ __launch_bounds__(256)
void x16_kernel(const float* __restrict__ x) {
    const size_t i8 = ((size_t)blockIdx.x * 256 + threadIdx.x) * 8;
    float4 v0 = reinterpret_cast<const float4*>(x + i8)[0];
    float4 v1 = reinterpret_cast<const float4*>(x + i8)[1];
    uint4 o;
    o.x = pack_f16(v0.x, v0.y);
    o.y = pack_f16(v0.z, v0.w);
    o.z = pack_f16(v1.x, v1.y);
    o.w = pack_f16(v1.z, v1.w);
    *reinterpret_cast<uint4*>(g_x16 + i8) = o;
}

// ---------------------------------------------------------------------------
// Kernel 0b: w16 = (qweight - zeros) * scales in fp16 (scale folded in)
// ---------------------------------------------------------------------------
__global__ __launch_bounds__(256)
void pack_w16(const int* __restrict__ qw, const int* __restrict__ zeros,
              const float* __restrict__ scales) {
    const size_t base = ((size_t)blockIdx.x * 256 + threadIdx.x) * 8;
    const int o = (int)(base >> 12);
    const int i = (int)(base & 4095);
    const int g = o * G_DIM + (i >> 7);
    const float z = (float)zeros[g];
    const float s = scales[g];
    const float nz = -z * s;
    int4 a = reinterpret_cast<const int4*>(qw + base)[0];
    int4 b = reinterpret_cast<const int4*>(qw + base)[1];
    uint4 w;
    w.x = pack_f16(fmaf((float)a.x, s, nz), fmaf((float)a.y, s, nz));
    w.y = pack_f16(fmaf((float)a.z, s, nz), fmaf((float)a.w, s, nz));
    w.z = pack_f16(fmaf((float)b.x, s, nz), fmaf((float)b.y, s, nz));
    w.w = pack_f16(fmaf((float)b.z, s, nz), fmaf((float)b.w, s, nz));
    *reinterpret_cast<uint4*>(g_w16 + base) = w;
}

// ---------------------------------------------------------------------------
// Kernel 1: xa[m, r] = SCALING * sum_k x[m,k] * lora_A[r,k]
// ---------------------------------------------------------------------------
__global__ __launch_bounds__(256)
void lora_xa_kernel(const float* __restrict__ x, const float* __restrict__ loraA) {
    const int m   = blockIdx.x;
    const int tid = threadIdx.x;
    const int lid = tid & 31;
    const int wid = tid >> 5;

    float acc[R_DIM];
#pragma unroll
    for (int r = 0; r < R_DIM; r++) acc[r] = 0.f;

    const float4* x4 = reinterpret_cast<const float4*>(x + (size_t)m * K_DIM);
    const float4* a4 = reinterpret_cast<const float4*>(loraA);
#pragma unroll
    for (int i = 0; i < 4; i++) {
        int f = tid + i * 256;
        float4 xv = x4[f];
#pragma unroll
        for (int r = 0; r < R_DIM; r++) {
            float4 av = a4[r * (K_DIM / 4) + f];
            acc[r] = fmaf(xv.x, av.x, acc[r]);
            acc[r] = fmaf(xv.y, av.y, acc[r]);
            acc[r] = fmaf(xv.z, av.z, acc[r]);
            acc[r] = fmaf(xv.w, av.w, acc[r]);
        }
    }
#pragma unroll
    for (int r = 0; r < R_DIM; r++) {
#pragma unroll
        for (int o = 16; o > 0; o >>= 1)
            acc[r] += __shfl_xor_sync(0xFFFFFFFFu, acc[r], o);
    }
    __shared__ float red[8][R_DIM];
    if (lid == 0) {
#pragma unroll
        for (int r = 0; r < R_DIM; r++) red[wid][r] = acc[r];
    }
    __syncthreads();
    if (tid < R_DIM) {
        float v = 0.f;
#pragma unroll
        for (int w = 0; w < 8; w++) v += red[w][tid];
        g_xa[m * R_DIM + tid] = v * SCALING;
    }
}

// ---------------------------------------------------------------------------
// Kernel 2: main GEMM. CTA 64x64, 128 threads, 4 warps (2m x 2n, 32x32 each),
// BK=32, 4-stage cp.async ring, distance-3 prefetch, 5 CTAs/SM.
// Scales pre-folded; tac accumulates f32 directly; LoRA k16 epilogue.
// ---------------------------------------------------------------------------
__global__ __launch_bounds__(128, 5)
void gptq_lora_mma(const float* __restrict__ loraB,
                   float*       __restrict__ out) {
    extern __shared__ __align__(16) char sm[];
    const uint32_t sb = smem_u32(sm);

    const int tid  = threadIdx.x;
    const int lane = tid & 31;
    const int wid  = tid >> 5;
    const int m0   = blockIdx.x * BM;    // 4 m-tiles (fastest -> w16 L2 dedup)
    const int n0   = blockIdx.y * BN;    // 172 n-tiles

    // ---- loader mappings: 64 rows x 64B per tile; 2 threads/row, 32B each ----
    const int lrow = tid >> 1;
    const int lhal = (tid & 1) * 32;                 // byte offset in row
    const __half* ag = g_x16 + (size_t)(m0 + lrow) * K_DIM + (lhal >> 1);
    const __half* bg = g_w16 + (size_t)(n0 + lrow) * K_DIM + (lhal >> 1);
    const uint32_t l_soff = (uint32_t)(lrow * PITCH + lhal);

    // ---- prologue: stages 0..2 ----
#pragma unroll
    for (int s = 0; s < 3; s++) {
        const uint32_t As = sb + s * A_ST;
        const uint32_t Bs = sb + B_BASE + s * B_ST;
        cpa16(As + l_soff,      ag + s * BK);
        cpa16(As + l_soff + 16, ag + s * BK + 8);
        cpa16(Bs + l_soff,      bg + s * BK);
        cpa16(Bs + l_soff + 16, bg + s * BK + 8);
        cpa_commit();
    }

    // ---- accumulators / compute mappings ----
    float tac[2][4][4];
#pragma unroll
    for (int mi = 0; mi < 2; mi++)
#pragma unroll
        for (int ni = 0; ni < 4; ni++)
#pragma unroll
            for (int j = 0; j < 4; j++) tac[mi][ni][j] = 0.f;

    const int wm = (wid >> 1) * 32;            // 0/32
    const int wn = (wid & 1) * 32;             // 0/32
    const uint32_t aoff  = (uint32_t)((wm + (lane & 15)) * PITCH + ((lane >> 4) << 4));
    const uint32_t boff4 = (uint32_t)((wn + (lane & 7) + ((lane >> 4) << 3)) * PITCH
                                      + (((lane >> 3) & 1) << 4));

    cpa_wait2();          // stage 0 complete (own groups)
    __syncthreads();      // all threads' -> fully visible

    // frag double buffers
    uint32_t fa[2][2][4], fb[2][4][2];

    for (int kt = 0; kt < KT; kt++) {
        // 1. prefetch stage kt+3
        if (kt < KT - 3) {
            const int ks = kt + 3;
            const int st = ks & 3;
            const uint32_t As = sb + st * A_ST;
            const uint32_t Bs = sb + B_BASE + st * B_ST;
            cpa16(As + l_soff,      ag + ks * BK);
            cpa16(As + l_soff + 16, ag + ks * BK + 8);
            cpa16(Bs + l_soff,      bg + ks * BK);
            cpa16(Bs + l_soff + 16, bg + ks * BK + 8);
        }
        cpa_commit();

        // 2. compute stage kt&3: 2 x k16 HMMA, frag-double-buffered
        {
            const uint32_t Ab = sb + (uint32_t)((kt & 3) * A_ST) + aoff;
            const uint32_t Bb = sb + B_BASE + (uint32_t)((kt & 3) * B_ST) + boff4;

            // load kk=0 into buffer 0
#pragma unroll
            for (int mi = 0; mi < 2; mi++)
                ldsm_x4(Ab + mi * (16 * PITCH), fa[0][mi]);
#pragma unroll
            for (int nj = 0; nj < 2; nj++) {
                uint32_t t[4];
                ldsm_x4(Bb + nj * (16 * PITCH), t);
                fb[0][2 * nj][0] = t[0]; fb[0][2 * nj][1] = t[1];
                fb[0][2 * nj + 1][0] = t[2]; fb[0][2 * nj + 1][1] = t[3];
            }
#pragma unroll
            for (int kk = 0; kk < 2; kk++) {
                const int cur = kk & 1, nxt = cur ^ 1;
                if (kk < 1) {
                    const uint32_t kb = 32;   // second k16 half (16 fp16 = 32B)
#pragma unroll
                    for (int mi = 0; mi < 2; mi++)
                        ldsm_x4(Ab + mi * (16 * PITCH) + kb, fa[nxt][mi]);
#pragma unroll
                    for (int nj = 0; nj < 2; nj++) {
                        uint32_t t[4];
                        ldsm_x4(Bb + nj * (16 * PITCH) + kb, t);
                        fb[nxt][2 * nj][0] = t[0]; fb[nxt][2 * nj][1] = t[1];
                        fb[nxt][2 * nj + 1][0] = t[2]; fb[nxt][2 * nj + 1][1] = t[3];
                    }
                }
#pragma unroll
                for (int mi = 0; mi < 2; mi++)
#pragma unroll
                    for (int ni = 0; ni < 4; ni++)
                        mma_f16(tac[mi][ni], fa[cur][mi], fb[cur][ni]);
            }
        }

        // 3. stage kt+1 complete; publish
        cpa_wait2();
        __syncthreads();
    }

    // ---- LoRA tiles: reuse stage-0 smem (all compute done) ----
    {
        const int row = tid & 63;
        const float* src = (tid < 64)
            ? (g_xa + (size_t)(m0 + row) * R_DIM)
            : (loraB + (size_t)(n0 + row) * R_DIM);
        char* dst = sm + ((tid < 64) ? SXA : SLB) + row * 32;
        float4 v0 = reinterpret_cast<const float4*>(src)[0];
        float4 v1 = reinterpret_cast<const float4*>(src)[1];
        float4 v2 = reinterpret_cast<const float4*>(src)[2];
        float4 v3 = reinterpret_cast<const float4*>(src)[3];
        *reinterpret_cast<uint4*>(dst) =
            make_uint4(pack_f16(v0.x, v0.y), pack_f16(v0.z, v0.w),
                       pack_f16(v1.x, v1.y), pack_f16(v1.z, v1.w));
        *reinterpret_cast<uint4*>(dst + 16) =
            make_uint4(pack_f16(v2.x, v2.y), pack_f16(v2.z, v2.w),
                       pack_f16(v3.x, v3.y), pack_f16(v3.z, v3.w));
    }
    __syncthreads();

    // ---- LoRA k16 step ----
    {
        uint32_t ah[2][4], b[4][2];
#pragma unroll
        for (int mi = 0; mi < 2; mi++)
            ldsm_x4(sb + SXA + (uint32_t)((wm + mi * 16 + (lane & 15)) * 32
                                          + ((lane >> 4) << 4)), ah[mi]);
#pragma unroll
        for (int ni = 0; ni < 4; ni++)
            ldsm_x2(sb + SLB + (uint32_t)((wn + ni * 8 + (lane & 7)) * 32
                                          + (((lane >> 3) & 1) << 4)), b[ni]);
#pragma unroll
        for (int mi = 0; mi < 2; mi++)
#pragma unroll
            for (int ni = 0; ni < 4; ni++)
                mma_f16(tac[mi][ni], ah[mi], b[ni]);
    }

    // ---- store ----
    {
        const int r  = lane >> 2;
        const int c2 = (lane & 3) * 2;
#pragma unroll
        for (int mi = 0; mi < 2; mi++) {
#pragma unroll
            for (int ni = 0; ni < 4; ni++) {
                const int m = m0 + wm + mi * 16 + r;
                const int n = n0 + wn + ni * 8 + c2;
                float* p = out + (size_t)m * N_DIM + n;
                *reinterpret_cast<float2*>(p) =
                    make_float2(tac[mi][ni][0], tac[mi][ni][1]);
                *reinterpret_cast<float2*>(p + 8 * (size_t)N_DIM) =
                    make_float2(tac[mi][ni][2], tac[mi][ni][3]);
            }
        }
    }
}

// ---------------------------------------------------------------------------
// kernel_launch — inputs: x, qweight, scales, zeros, lora_A, lora_B
// ---------------------------------------------------------------------------
extern "C" void kernel_launch(void* const* d_in, const int* in_sizes, int n_in,
                              void* d_out, int out_size) {
    const float* x      = (const float*)d_in[0];
    const int*   qw     = (const int*)  d_in[1];
    const float* scales = (const float*)d_in[2];
    const int*   zeros  = (const int*)  d_in[3];
    const float* loraA  = (const float*)d_in[4];
    const float* loraB  = (const float*)d_in[5];
    float*       out    = (float*)d_out;

    cudaFuncSetAttribute(gptq_lora_mma,
                         cudaFuncAttributeMaxDynamicSharedMemorySize, SMEM_BYTES);

    x16_kernel<<<(int)(((size_t)M_DIM * K_DIM) / (256 * 8)), 256>>>(x);
    pack_w16<<<(int)(((size_t)N_DIM * K_DIM) / (256 * 8)), 256>>>(qw, zeros, scales);
    lora_xa_kernel<<<M_DIM, 256>>>(x, loraA);

    dim3 grid(M_DIM / BM, N_DIM / BN);   // (4, 172): m fastest -> w16 L2 dedup
    gptq_lora_mma<<<grid, 128, SMEM_BYTES>>>(loraB, out);
}